// round 1
// baseline (speedup 1.0000x reference)
#include <cuda_runtime.h>

#define NN   100000
#define DIMC 64
#define HH   4

// Scratch (allocation-free rule: __device__ globals)
__device__ float g_q[NN * DIMC];
__device__ float g_k[NN * DIMC];
__device__ float g_v[NN * DIMC];
__device__ float g_acc[NN * DIMC];
__device__ float g_den[NN * HH];

// ---------------------------------------------------------------------------
// Zero the accumulators (d_out is poisoned; scratch must be re-zeroed per call)
// ---------------------------------------------------------------------------
__global__ void zero_kernel() {
    int i = blockIdx.x * blockDim.x + threadIdx.x;
    int stride = gridDim.x * blockDim.x;
    float4 z = make_float4(0.f, 0.f, 0.f, 0.f);
    const int n4 = (NN * DIMC) / 4;
    for (int j = i; j < n4; j += stride) ((float4*)g_acc)[j] = z;
    const int nd = (NN * HH) / 4;
    for (int j = i; j < nd; j += stride) ((float4*)g_den)[j] = z;
}

// ---------------------------------------------------------------------------
// Projection: out[n] = x[n] @ W^T + b   (W row-major [64][64])
// blockIdx.y selects (query,Wq)->g_q, (key,Wk)->g_k, (value,Wv)->g_v.
// One warp per node; W transposed into smem so each lane reads a conflict-free
// float2 column pair; input row broadcast via shfl.
// ---------------------------------------------------------------------------
__global__ void proj_kernel(const float* __restrict__ query,
                            const float* __restrict__ key,
                            const float* __restrict__ value,
                            const float* __restrict__ Wq, const float* __restrict__ bq,
                            const float* __restrict__ Wk, const float* __restrict__ bk,
                            const float* __restrict__ Wv, const float* __restrict__ bv)
{
    __shared__ float sW[DIMC * DIMC];
    __shared__ float sb[DIMC];

    const float* x_in; const float* W; const float* b; float* out;
    int m = blockIdx.y;
    if (m == 0)      { x_in = query; W = Wq; b = bq; out = g_q; }
    else if (m == 1) { x_in = key;   W = Wk; b = bk; out = g_k; }
    else             { x_in = value; W = Wv; b = bv; out = g_v; }

    // sW[i*64 + j] = W[j][i]  (transpose)
    for (int idx = threadIdx.x; idx < DIMC * DIMC; idx += blockDim.x) {
        int j = idx >> 6, i = idx & 63;
        sW[i * DIMC + j] = W[idx];
    }
    if (threadIdx.x < DIMC) sb[threadIdx.x] = b[threadIdx.x];
    __syncthreads();

    int wid = threadIdx.x >> 5, lane = threadIdx.x & 31;
    int node = blockIdx.x * 8 + wid;
    if (node >= NN) return;

    float2 xv = ((const float2*)(x_in + (size_t)node * DIMC))[lane];
    float2 acc = make_float2(0.f, 0.f);
#pragma unroll
    for (int i = 0; i < DIMC; i++) {
        float xi = __shfl_sync(0xffffffffu, (i & 1) ? xv.y : xv.x, i >> 1);
        float2 w = *(const float2*)(sW + i * DIMC + 2 * lane);
        acc.x += xi * w.x;
        acc.y += xi * w.y;
    }
    float2 bb = ((const float2*)sb)[lane];
    ((float2*)(out + (size_t)node * DIMC))[lane] =
        make_float2(acc.x + bb.x, acc.y + bb.y);
}

// ---------------------------------------------------------------------------
// Edge kernel: per edge e, score_h = dot16(q[dst],k[src]) / 4; ex = exp(score);
// acc[dst] += ex_h * v[src]; den[dst][h] += ex_h.
// Half-warp (16 lanes x float4) per edge; no segment-max needed (fp32 safe).
// ---------------------------------------------------------------------------
__global__ void edge_kernel(const int* __restrict__ src,
                            const int* __restrict__ dst, int E)
{
    long long t = (long long)blockIdx.x * blockDim.x + threadIdx.x;
    int e    = (int)(t >> 4);
    int lane = threadIdx.x & 31;
    int sub  = lane & 15;          // lane within edge group
    bool valid = e < E;
    int s = 0, d = 0;
    if (valid) { s = src[e]; d = dst[e]; }

    float4 qv = *(const float4*)(g_q + (size_t)d * DIMC + sub * 4);
    float4 kv = *(const float4*)(g_k + (size_t)s * DIMC + sub * 4);
    float p = qv.x * kv.x + qv.y * kv.y + qv.z * kv.z + qv.w * kv.w;
    // reduce within 4-lane head group (head = sub/4, 16 dims = 4 lanes x 4)
    p += __shfl_xor_sync(0xffffffffu, p, 1);
    p += __shfl_xor_sync(0xffffffffu, p, 2);
    float ex = __expf(p * 0.25f);   // 1/sqrt(DK)=0.25; scores O(1), no max needed

    float4 vv = *(const float4*)(g_v + (size_t)s * DIMC + sub * 4);
    if (valid) {
        float* ap = g_acc + (size_t)d * DIMC + sub * 4;
        asm volatile("red.global.add.v4.f32 [%0], {%1,%2,%3,%4};"
                     :: "l"(ap), "f"(ex * vv.x), "f"(ex * vv.y),
                        "f"(ex * vv.z), "f"(ex * vv.w) : "memory");
    }
    // one vector red for the 4 head denominators (lane sub==0 of each half-warp)
    int hb = lane & 16;
    float e0 = __shfl_sync(0xffffffffu, ex, hb + 0);
    float e1 = __shfl_sync(0xffffffffu, ex, hb + 4);
    float e2 = __shfl_sync(0xffffffffu, ex, hb + 8);
    float e3 = __shfl_sync(0xffffffffu, ex, hb + 12);
    if (valid && sub == 0) {
        float* dp = g_den + (size_t)d * HH;
        asm volatile("red.global.add.v4.f32 [%0], {%1,%2,%3,%4};"
                     :: "l"(dp), "f"(e0), "f"(e1), "f"(e2), "f"(e3) : "memory");
    }
}

// ---------------------------------------------------------------------------
// Final: x[n][j] = acc[n][j]/den[n][j/16]; out[n] = x @ Wo^T + bo
// ---------------------------------------------------------------------------
__global__ void final_kernel(const float* __restrict__ Wo,
                             const float* __restrict__ bo,
                             float* __restrict__ out)
{
    __shared__ float sW[DIMC * DIMC];
    __shared__ float sb[DIMC];
    for (int idx = threadIdx.x; idx < DIMC * DIMC; idx += blockDim.x) {
        int j = idx >> 6, i = idx & 63;
        sW[i * DIMC + j] = Wo[idx];
    }
    if (threadIdx.x < DIMC) sb[threadIdx.x] = bo[threadIdx.x];
    __syncthreads();

    int wid = threadIdx.x >> 5, lane = threadIdx.x & 31;
    int node = blockIdx.x * 8 + wid;
    if (node >= NN) return;

    float2 a = ((const float2*)(g_acc + (size_t)node * DIMC))[lane];
    float den = g_den[(size_t)node * HH + (lane >> 3)];  // head = (2*lane)/16
    float inv = (den > 0.f) ? (1.f / den) : 0.f;          // isolated-node guard
    float2 xv = make_float2(a.x * inv, a.y * inv);

    float2 acc = make_float2(0.f, 0.f);
#pragma unroll
    for (int i = 0; i < DIMC; i++) {
        float xi = __shfl_sync(0xffffffffu, (i & 1) ? xv.y : xv.x, i >> 1);
        float2 w = *(const float2*)(sW + i * DIMC + 2 * lane);
        acc.x += xi * w.x;
        acc.y += xi * w.y;
    }
    float2 bb = ((const float2*)sb)[lane];
    ((float2*)(out + (size_t)node * DIMC))[lane] =
        make_float2(acc.x + bb.x, acc.y + bb.y);
}

// ---------------------------------------------------------------------------
extern "C" void kernel_launch(void* const* d_in, const int* in_sizes, int n_in,
                              void* d_out, int out_size)
{
    const float* query = (const float*)d_in[0];
    const float* key   = (const float*)d_in[1];
    const float* value = (const float*)d_in[2];
    const int*   src   = (const int*)d_in[3];
    const int*   dst   = (const int*)d_in[4];
    const float* Wq = (const float*)d_in[5];  const float* bq = (const float*)d_in[6];
    const float* Wk = (const float*)d_in[7];  const float* bk = (const float*)d_in[8];
    const float* Wv = (const float*)d_in[9];  const float* bv = (const float*)d_in[10];
    const float* Wo = (const float*)d_in[11]; const float* bo = (const float*)d_in[12];
    int E = in_sizes[3];

    zero_kernel<<<2048, 256>>>();

    dim3 pg((NN + 7) / 8, 3);
    proj_kernel<<<pg, 256>>>(query, key, value, Wq, bq, Wk, bk, Wv, bv);

    long long ethreads = (long long)E * 16;
    int eblocks = (int)((ethreads + 255) / 256);
    edge_kernel<<<eblocks, 256>>>(src, dst, E);

    final_kernel<<<(NN + 7) / 8, 256>>>(Wo, bo, (float*)d_out);
}

// round 3
// speedup vs baseline: 3.1334x; 3.1334x over previous
#include <cuda_runtime.h>

#define NN   100000
#define DIMC 64
#define HH   4

// Scratch (allocation-free rule: __device__ globals)
__device__ float g_q[NN * DIMC];
__device__ float g_k[NN * DIMC];
__device__ float g_v[NN * DIMC];
__device__ float g_acc[NN * DIMC];
__device__ float g_den[NN * HH];

// ---------------------------------------------------------------------------
// Zero the accumulators
// ---------------------------------------------------------------------------
__global__ void zero_kernel() {
    int i = blockIdx.x * blockDim.x + threadIdx.x;
    int stride = gridDim.x * blockDim.x;
    float4 z = make_float4(0.f, 0.f, 0.f, 0.f);
    const int n4 = (NN * DIMC) / 4;
    for (int j = i; j < n4; j += stride) ((float4*)g_acc)[j] = z;
    const int nd = (NN * HH) / 4;
    for (int j = i; j < nd; j += stride) ((float4*)g_den)[j] = z;
}

// ---------------------------------------------------------------------------
// Register-blocked GEMM body: out[node] = X[node] @ W^T + b
// Tile: 128 nodes x 64 cols per block of 256 threads.
// Thread micro-tile: 4 nodes x 8 cols (32 accumulators).
// DIV_DEN: X is g_acc; divide each element by its head's softmax denominator
// during the smem load (fused epilogue of the edge phase).
// ---------------------------------------------------------------------------
template <bool DIV_DEN>
__device__ __forceinline__ void gemm64(const float* __restrict__ X,
                                       const float* __restrict__ W,
                                       const float* __restrict__ bias,
                                       float* __restrict__ out,
                                       const float* __restrict__ den)
{
    __shared__ float sX[128][DIMC];   // row-major copy of the node tile
    __shared__ float sW[DIMC][DIMC];  // sW[k][c] = W[c][k]

    int tid  = threadIdx.x;
    int base = blockIdx.x * 128;

    // W transpose into smem (one-time, 4096 floats)
    for (int idx = tid; idx < DIMC * DIMC; idx += 256) {
        int c = idx >> 6, k = idx & 63;
        sW[k][c] = W[idx];
    }

    // X tile: 2048 float4, 8 per thread, fully coalesced, conflict-free STS
#pragma unroll
    for (int i = 0; i < 8; i++) {
        int idx  = tid + i * 256;       // float4 index within tile
        int row  = idx >> 4;            // 16 float4 per row
        int c4   = idx & 15;
        int node = base + row;
        float4 xv = make_float4(0.f, 0.f, 0.f, 0.f);
        if (node < NN) {
            xv = ((const float4*)(X + (size_t)node * DIMC))[c4];
            if (DIV_DEN) {
                float dd  = den[node * HH + (c4 >> 2)];   // head = (4*c4)/16
                float inv = (dd > 0.f) ? (1.f / dd) : 0.f;
                xv.x *= inv; xv.y *= inv; xv.z *= inv; xv.w *= inv;
            }
        }
        *(float4*)&sX[row][c4 * 4] = xv;
    }
    __syncthreads();

    int cg = tid & 7;    // col group: cols cg*8 .. cg*8+7
    int ng = tid >> 3;   // node group: rows ng*4 .. ng*4+3

    float acc[4][8];
#pragma unroll
    for (int r = 0; r < 4; r++)
#pragma unroll
        for (int c = 0; c < 8; c++) acc[r][c] = 0.f;

#pragma unroll 4
    for (int k4 = 0; k4 < DIMC; k4 += 4) {
        float4 xr[4];
#pragma unroll
        for (int r = 0; r < 4; r++)
            xr[r] = *(const float4*)&sX[ng * 4 + r][k4];
#pragma unroll
        for (int kk = 0; kk < 4; kk++) {
            float4 w0 = *(const float4*)&sW[k4 + kk][cg * 8];
            float4 w1 = *(const float4*)&sW[k4 + kk][cg * 8 + 4];
#pragma unroll
            for (int r = 0; r < 4; r++) {
                float x = (kk == 0) ? xr[r].x : (kk == 1) ? xr[r].y
                        : (kk == 2) ? xr[r].z : xr[r].w;
                acc[r][0] += x * w0.x;  acc[r][1] += x * w0.y;
                acc[r][2] += x * w0.z;  acc[r][3] += x * w0.w;
                acc[r][4] += x * w1.x;  acc[r][5] += x * w1.y;
                acc[r][6] += x * w1.z;  acc[r][7] += x * w1.w;
            }
        }
    }

    // Bias straight from L2 (tiny, fully cached)
    float4 b0 = ((const float4*)(bias + cg * 8))[0];
    float4 b1 = ((const float4*)(bias + cg * 8))[1];

#pragma unroll
    for (int r = 0; r < 4; r++) {
        int node = base + ng * 4 + r;
        if (node >= NN) continue;
        float4 o0 = make_float4(acc[r][0] + b0.x, acc[r][1] + b0.y,
                                acc[r][2] + b0.z, acc[r][3] + b0.w);
        float4 o1 = make_float4(acc[r][4] + b1.x, acc[r][5] + b1.y,
                                acc[r][6] + b1.z, acc[r][7] + b1.w);
        float4* op = (float4*)(out + (size_t)node * DIMC + cg * 8);
        op[0] = o0;
        op[1] = o1;
    }
}

// Projections: blockIdx.y selects (query,Wq)->g_q, (key,Wk)->g_k, (value,Wv)->g_v
__global__ __launch_bounds__(256)
void proj_kernel(const float* __restrict__ query,
                 const float* __restrict__ key,
                 const float* __restrict__ value,
                 const float* __restrict__ Wq, const float* __restrict__ bq,
                 const float* __restrict__ Wk, const float* __restrict__ bk,
                 const float* __restrict__ Wv, const float* __restrict__ bv)
{
    int m = blockIdx.y;
    if (m == 0)      gemm64<false>(query, Wq, bq, g_q, nullptr);
    else if (m == 1) gemm64<false>(key,   Wk, bk, g_k, nullptr);
    else             gemm64<false>(value, Wv, bv, g_v, nullptr);
}

// Final: (g_acc / den) @ Wo^T + bo -> d_out
__global__ __launch_bounds__(256)
void final_kernel(const float* __restrict__ Wo,
                  const float* __restrict__ bo,
                  float* __restrict__ out)
{
    gemm64<true>(g_acc, Wo, bo, out, g_den);
}

// ---------------------------------------------------------------------------
// Edge kernel: per edge e, score_h = dot16(q[dst],k[src]) / 4; ex = exp(score);
// acc[dst] += ex_h * v[src]; den[dst][h] += ex_h.
// Half-warp (16 lanes x float4) per edge; no segment-max needed (fp32 safe).
// ---------------------------------------------------------------------------
__global__ void edge_kernel(const int* __restrict__ src,
                            const int* __restrict__ dst, int E)
{
    long long t = (long long)blockIdx.x * blockDim.x + threadIdx.x;
    int e    = (int)(t >> 4);
    int lane = threadIdx.x & 31;
    int sub  = lane & 15;          // lane within edge group
    bool valid = e < E;
    int s = 0, d = 0;
    if (valid) { s = src[e]; d = dst[e]; }

    float4 qv = *(const float4*)(g_q + (size_t)d * DIMC + sub * 4);
    float4 kv = *(const float4*)(g_k + (size_t)s * DIMC + sub * 4);
    float p = qv.x * kv.x + qv.y * kv.y + qv.z * kv.z + qv.w * kv.w;
    // reduce within 4-lane head group (head = sub/4, 16 dims = 4 lanes x 4)
    p += __shfl_xor_sync(0xffffffffu, p, 1);
    p += __shfl_xor_sync(0xffffffffu, p, 2);
    float ex = __expf(p * 0.25f);   // 1/sqrt(DK)=0.25; scores O(1), no max needed

    float4 vv = *(const float4*)(g_v + (size_t)s * DIMC + sub * 4);
    if (valid) {
        float* ap = g_acc + (size_t)d * DIMC + sub * 4;
        asm volatile("red.global.add.v4.f32 [%0], {%1,%2,%3,%4};"
                     :: "l"(ap), "f"(ex * vv.x), "f"(ex * vv.y),
                        "f"(ex * vv.z), "f"(ex * vv.w) : "memory");
    }
    // one vector red for the 4 head denominators (lane sub==0 of each half-warp)
    int hb = lane & 16;
    float e0 = __shfl_sync(0xffffffffu, ex, hb + 0);
    float e1 = __shfl_sync(0xffffffffu, ex, hb + 4);
    float e2 = __shfl_sync(0xffffffffu, ex, hb + 8);
    float e3 = __shfl_sync(0xffffffffu, ex, hb + 12);
    if (valid && sub == 0) {
        float* dp = g_den + (size_t)d * HH;
        asm volatile("red.global.add.v4.f32 [%0], {%1,%2,%3,%4};"
                     :: "l"(dp), "f"(e0), "f"(e1), "f"(e2), "f"(e3) : "memory");
    }
}

// ---------------------------------------------------------------------------
extern "C" void kernel_launch(void* const* d_in, const int* in_sizes, int n_in,
                              void* d_out, int out_size)
{
    const float* query = (const float*)d_in[0];
    const float* key   = (const float*)d_in[1];
    const float* value = (const float*)d_in[2];
    const int*   src   = (const int*)d_in[3];
    const int*   dst   = (const int*)d_in[4];
    const float* Wq = (const float*)d_in[5];  const float* bq = (const float*)d_in[6];
    const float* Wk = (const float*)d_in[7];  const float* bk = (const float*)d_in[8];
    const float* Wv = (const float*)d_in[9];  const float* bv = (const float*)d_in[10];
    const float* Wo = (const float*)d_in[11]; const float* bo = (const float*)d_in[12];
    int E = in_sizes[3];

    zero_kernel<<<2048, 256>>>();

    dim3 pg((NN + 127) / 128, 3);
    proj_kernel<<<pg, 256>>>(query, key, value, Wq, bq, Wk, bk, Wv, bv);

    long long ethreads = (long long)E * 16;
    int eblocks = (int)((ethreads + 255) / 256);
    edge_kernel<<<eblocks, 256>>>(src, dst, E);

    final_kernel<<<(NN + 127) / 128, 256>>>(Wo, bo, (float*)d_out);
}

// round 4
// speedup vs baseline: 3.5235x; 1.1245x over previous
#include <cuda_runtime.h>

#define NN   100000
#define DIMC 64
#define HH   4

// Scratch (allocation-free rule: __device__ globals)
__device__ float g_q[NN * DIMC];
__device__ float g_k[NN * DIMC];
__device__ float g_v[NN * DIMC];
__device__ float g_acc[NN * DIMC];
__device__ float g_den[NN * HH];

// ---------------------------------------------------------------------------
// Zero the accumulators
// ---------------------------------------------------------------------------
__global__ void zero_kernel() {
    int i = blockIdx.x * blockDim.x + threadIdx.x;
    int stride = gridDim.x * blockDim.x;
    float4 z = make_float4(0.f, 0.f, 0.f, 0.f);
    const int n4 = (NN * DIMC) / 4;
    for (int j = i; j < n4; j += stride) ((float4*)g_acc)[j] = z;
    const int nd = (NN * HH) / 4;
    for (int j = i; j < nd; j += stride) ((float4*)g_den)[j] = z;
}

// ---------------------------------------------------------------------------
// Register-blocked GEMM: out[node] = X[node] @ W^T + b   (W row-major [c][k])
// Block: 128 threads, tile 128 nodes x 64 cols; micro-tile 8 nodes x 8 cols.
// Inner product form: acc[r][j] += dot4(x[row_r][k4], W[c_j][k4]) — W needs NO
// transpose; both smem arrays are XOR-swizzled so every LDS is conflict-free:
//   sX4[row*16 + (kc ^ (row&15))]   rows per thread strided by 16 => within a
//                                   warp rows differ in low bits => 4 distinct
//                                   16B banks per x-load (broadcast x8).
//   sW4[c*16 + (kc ^ cg)]           cg = c>>3; the 8 simultaneous w-addresses
//                                   (c = cg*8+j, cg=0..7) hit 8 distinct banks.
// Bytes/FFMA = 1.0 -> crossbar time == FFMA time (balanced).
// DIV_DEN: X is g_acc; divide by per-head softmax denominator during load.
// ---------------------------------------------------------------------------
template <bool DIV_DEN>
__device__ __forceinline__ void gemm64(const float* __restrict__ X,
                                       const float* __restrict__ W,
                                       const float* __restrict__ bias,
                                       float* __restrict__ out,
                                       const float* __restrict__ den)
{
    __shared__ float4 sX4[128 * 16];   // 32 KB, swizzled
    __shared__ float4 sW4[64 * 16];    // 16 KB, swizzled (row-major W copy)

    int tid  = threadIdx.x;
    int base = blockIdx.x * 128;

    // W copy-in: 1024 float4, identity layout + swizzle. Coalesced LDG.
#pragma unroll
    for (int i = 0; i < 8; i++) {
        int idx = tid + i * 128;
        int c   = idx >> 4;
        int kc  = idx & 15;
        sW4[c * 16 + (kc ^ ((c >> 3) & 7))] = ((const float4*)W)[idx];
    }

    // X tile: 2048 float4. Coalesced LDG, swizzled STS.
#pragma unroll
    for (int i = 0; i < 16; i++) {
        int idx  = tid + i * 128;
        int row  = idx >> 4;
        int c4   = idx & 15;
        int node = base + row;
        float4 xv = make_float4(0.f, 0.f, 0.f, 0.f);
        if (node < NN) {
            xv = ((const float4*)(X + (size_t)node * DIMC))[c4];
            if (DIV_DEN) {
                float dd  = den[node * HH + (c4 >> 2)];   // head = (4*c4)/16
                float inv = (dd > 0.f) ? (1.f / dd) : 0.f;
                xv.x *= inv; xv.y *= inv; xv.z *= inv; xv.w *= inv;
            }
        }
        sX4[row * 16 + (c4 ^ (row & 15))] = xv;
    }
    __syncthreads();

    int cg = tid & 7;    // col group: cols cg*8 .. cg*8+7
    int ng = tid >> 3;   // node group: rows ng, ng+16, ..., ng+112

    float acc[8][8];
#pragma unroll
    for (int r = 0; r < 8; r++)
#pragma unroll
        for (int j = 0; j < 8; j++) acc[r][j] = 0.f;

#pragma unroll
    for (int kc = 0; kc < 16; kc++) {
        float4 wv[8];
#pragma unroll
        for (int j = 0; j < 8; j++)
            wv[j] = sW4[(cg * 8 + j) * 16 + (kc ^ cg)];
#pragma unroll
        for (int r = 0; r < 8; r++) {
            float4 xv = sX4[(ng + 16 * r) * 16 + (kc ^ ng)];
#pragma unroll
            for (int j = 0; j < 8; j++) {
                acc[r][j] += xv.x * wv[j].x;
                acc[r][j] += xv.y * wv[j].y;
                acc[r][j] += xv.z * wv[j].z;
                acc[r][j] += xv.w * wv[j].w;
            }
        }
    }

    // Bias straight from L1/L2 (tiny, fully cached)
    float4 b0 = ((const float4*)(bias + cg * 8))[0];
    float4 b1 = ((const float4*)(bias + cg * 8))[1];

#pragma unroll
    for (int r = 0; r < 8; r++) {
        int node = base + ng + 16 * r;
        if (node >= NN) continue;
        float4 o0 = make_float4(acc[r][0] + b0.x, acc[r][1] + b0.y,
                                acc[r][2] + b0.z, acc[r][3] + b0.w);
        float4 o1 = make_float4(acc[r][4] + b1.x, acc[r][5] + b1.y,
                                acc[r][6] + b1.z, acc[r][7] + b1.w);
        float4* op = (float4*)(out + (size_t)node * DIMC + cg * 8);
        op[0] = o0;
        op[1] = o1;
    }
}

// Projections: blockIdx.y selects (query,Wq)->g_q, (key,Wk)->g_k, (value,Wv)->g_v
__global__ __launch_bounds__(128)
void proj_kernel(const float* __restrict__ query,
                 const float* __restrict__ key,
                 const float* __restrict__ value,
                 const float* __restrict__ Wq, const float* __restrict__ bq,
                 const float* __restrict__ Wk, const float* __restrict__ bk,
                 const float* __restrict__ Wv, const float* __restrict__ bv)
{
    int m = blockIdx.y;
    if (m == 0)      gemm64<false>(query, Wq, bq, g_q, nullptr);
    else if (m == 1) gemm64<false>(key,   Wk, bk, g_k, nullptr);
    else             gemm64<false>(value, Wv, bv, g_v, nullptr);
}

// Final: (g_acc / den) @ Wo^T + bo -> d_out
__global__ __launch_bounds__(128)
void final_kernel(const float* __restrict__ Wo,
                  const float* __restrict__ bo,
                  float* __restrict__ out)
{
    gemm64<true>(g_acc, Wo, bo, out, g_den);
}

// ---------------------------------------------------------------------------
// Edge kernel: per edge e, score_h = dot16(q[dst],k[src]) / 4; ex = exp(score);
// acc[dst] += ex_h * v[src]; den[dst][h] += ex_h.
// Half-warp (16 lanes x float4) per edge; no segment-max needed (fp32 safe).
// ---------------------------------------------------------------------------
__global__ void edge_kernel(const int* __restrict__ src,
                            const int* __restrict__ dst, int E)
{
    long long t = (long long)blockIdx.x * blockDim.x + threadIdx.x;
    int e    = (int)(t >> 4);
    int lane = threadIdx.x & 31;
    int sub  = lane & 15;          // lane within edge group
    bool valid = e < E;
    int s = 0, d = 0;
    if (valid) { s = src[e]; d = dst[e]; }

    float4 qv = *(const float4*)(g_q + (size_t)d * DIMC + sub * 4);
    float4 kv = *(const float4*)(g_k + (size_t)s * DIMC + sub * 4);
    float p = qv.x * kv.x + qv.y * kv.y + qv.z * kv.z + qv.w * kv.w;
    // reduce within 4-lane head group (head = sub/4, 16 dims = 4 lanes x 4)
    p += __shfl_xor_sync(0xffffffffu, p, 1);
    p += __shfl_xor_sync(0xffffffffu, p, 2);
    float ex = __expf(p * 0.25f);   // 1/sqrt(DK)=0.25; scores O(1), no max needed

    float4 vv = *(const float4*)(g_v + (size_t)s * DIMC + sub * 4);
    if (valid) {
        float* ap = g_acc + (size_t)d * DIMC + sub * 4;
        asm volatile("red.global.add.v4.f32 [%0], {%1,%2,%3,%4};"
                     :: "l"(ap), "f"(ex * vv.x), "f"(ex * vv.y),
                        "f"(ex * vv.z), "f"(ex * vv.w) : "memory");
    }
    // one vector red for the 4 head denominators (lane sub==0 of each half-warp)
    int hb = lane & 16;
    float e0 = __shfl_sync(0xffffffffu, ex, hb + 0);
    float e1 = __shfl_sync(0xffffffffu, ex, hb + 4);
    float e2 = __shfl_sync(0xffffffffu, ex, hb + 8);
    float e3 = __shfl_sync(0xffffffffu, ex, hb + 12);
    if (valid && sub == 0) {
        float* dp = g_den + (size_t)d * HH;
        asm volatile("red.global.add.v4.f32 [%0], {%1,%2,%3,%4};"
                     :: "l"(dp), "f"(e0), "f"(e1), "f"(e2), "f"(e3) : "memory");
    }
}

// ---------------------------------------------------------------------------
extern "C" void kernel_launch(void* const* d_in, const int* in_sizes, int n_in,
                              void* d_out, int out_size)
{
    const float* query = (const float*)d_in[0];
    const float* key   = (const float*)d_in[1];
    const float* value = (const float*)d_in[2];
    const int*   src   = (const int*)d_in[3];
    const int*   dst   = (const int*)d_in[4];
    const float* Wq = (const float*)d_in[5];  const float* bq = (const float*)d_in[6];
    const float* Wk = (const float*)d_in[7];  const float* bk = (const float*)d_in[8];
    const float* Wv = (const float*)d_in[9];  const float* bv = (const float*)d_in[10];
    const float* Wo = (const float*)d_in[11]; const float* bo = (const float*)d_in[12];
    int E = in_sizes[3];

    zero_kernel<<<2048, 256>>>();

    dim3 pg((NN + 127) / 128, 3);
    proj_kernel<<<pg, 128>>>(query, key, value, Wq, bq, Wk, bk, Wv, bv);

    long long ethreads = (long long)E * 16;
    int eblocks = (int)((ethreads + 255) / 256);
    edge_kernel<<<eblocks, 256>>>(src, dst, E);

    final_kernel<<<(NN + 127) / 128, 128>>>(Wo, bo, (float*)d_out);
}

// round 6
// speedup vs baseline: 4.6091x; 1.3081x over previous
#include <cuda_runtime.h>
#include <cuda_fp16.h>

#define NN   100000
#define DIMC 64
#define HH   4

// Scratch (allocation-free rule: __device__ globals)
__device__ __half g_qh[NN * DIMC];
__device__ __half g_kh[NN * DIMC];
__device__ __half g_vh[NN * DIMC];
__device__ float  g_acc[NN * DIMC];
__device__ float  g_den[NN * HH];

// ---------------------------------------------------------------------------
// Zero the accumulators
// ---------------------------------------------------------------------------
__global__ void zero_kernel() {
    int i = blockIdx.x * blockDim.x + threadIdx.x;
    int stride = gridDim.x * blockDim.x;
    float4 z = make_float4(0.f, 0.f, 0.f, 0.f);
    const int n4 = (NN * DIMC) / 4;
    for (int j = i; j < n4; j += stride) ((float4*)g_acc)[j] = z;
    const int nd = (NN * HH) / 4;
    for (int j = i; j < nd; j += stride) ((float4*)g_den)[j] = z;
}

// ---------------------------------------------------------------------------
// Register-blocked GEMM: out[node] = X[node] @ W^T + b   (W row-major [c][k])
// Block: 256 threads, tile 128 nodes x 64 cols; micro-tile 8 nodes x 4 cols
// (32 accumulators -> ~80 regs -> 3 blocks = 24 warps/SM, 2x R4 occupancy).
// XOR-swizzled smem, conflict-free x loads, 2-way w loads (cheap vs FFMA).
// DIV_DEN: X is g_acc; divide by per-head softmax denominator during load.
// OUT_HALF: round the fp32 result to __half on store (q/k/v scratch).
// ---------------------------------------------------------------------------
template <bool DIV_DEN, bool OUT_HALF>
__device__ __forceinline__ void gemm64(const float* __restrict__ X,
                                       const float* __restrict__ W,
                                       const float* __restrict__ bias,
                                       void* __restrict__ out,
                                       const float* __restrict__ den)
{
    __shared__ float4 sX4[128 * 16];   // 32 KB, swizzled
    __shared__ float4 sW4[64 * 16];    // 16 KB, swizzled (row-major W copy)

    int tid  = threadIdx.x;
    int base = blockIdx.x * 128;

    // W copy-in: 1024 float4, identity layout + swizzle. Coalesced LDG.
#pragma unroll
    for (int i = 0; i < 4; i++) {
        int idx = tid + i * 256;
        int c   = idx >> 4;
        int kc  = idx & 15;
        sW4[c * 16 + (kc ^ ((c >> 3) & 7))] = ((const float4*)W)[idx];
    }

    // X tile: 2048 float4. Coalesced LDG, swizzled STS.
#pragma unroll
    for (int i = 0; i < 8; i++) {
        int idx  = tid + i * 256;
        int row  = idx >> 4;
        int c4   = idx & 15;
        int node = base + row;
        float4 xv = make_float4(0.f, 0.f, 0.f, 0.f);
        if (node < NN) {
            xv = ((const float4*)(X + (size_t)node * DIMC))[c4];
            if (DIV_DEN) {
                float dd  = den[node * HH + (c4 >> 2)];   // head = (4*c4)/16
                float inv = (dd > 0.f) ? (1.f / dd) : 0.f;
                xv.x *= inv; xv.y *= inv; xv.z *= inv; xv.w *= inv;
            }
        }
        sX4[row * 16 + (c4 ^ (row & 15))] = xv;
    }
    __syncthreads();

    int cg = tid & 15;   // col group: cols cg*4 .. cg*4+3
    int ng = tid >> 4;   // node group: rows ng, ng+16, ..., ng+112

    float acc[8][4];
#pragma unroll
    for (int r = 0; r < 8; r++)
#pragma unroll
        for (int j = 0; j < 4; j++) acc[r][j] = 0.f;

#pragma unroll
    for (int kc = 0; kc < 16; kc++) {
        float4 wv[4];
#pragma unroll
        for (int j = 0; j < 4; j++) {
            int c = cg * 4 + j;
            wv[j] = sW4[c * 16 + (kc ^ ((c >> 3) & 7))];
        }
#pragma unroll
        for (int r = 0; r < 8; r++) {
            float4 xv = sX4[(ng + 16 * r) * 16 + (kc ^ ng)];
#pragma unroll
            for (int j = 0; j < 4; j++) {
                acc[r][j] += xv.x * wv[j].x;
                acc[r][j] += xv.y * wv[j].y;
                acc[r][j] += xv.z * wv[j].z;
                acc[r][j] += xv.w * wv[j].w;
            }
        }
    }

    // Bias straight from L1/L2 (tiny, fully cached)
    float4 bb = *(const float4*)(bias + cg * 4);

#pragma unroll
    for (int r = 0; r < 8; r++) {
        int node = base + ng + 16 * r;
        if (node >= NN) continue;
        float4 o = make_float4(acc[r][0] + bb.x, acc[r][1] + bb.y,
                               acc[r][2] + bb.z, acc[r][3] + bb.w);
        if (OUT_HALF) {
            __half2 h0 = __float22half2_rn(make_float2(o.x, o.y));
            __half2 h1 = __float22half2_rn(make_float2(o.z, o.w));
            uint2 pk;
            pk.x = *(unsigned*)&h0;
            pk.y = *(unsigned*)&h1;
            *(uint2*)((__half*)out + (size_t)node * DIMC + cg * 4) = pk;
        } else {
            *(float4*)((float*)out + (size_t)node * DIMC + cg * 4) = o;
        }
    }
}

// Projections: blockIdx.y selects (query,Wq)->g_qh, (key,Wk)->g_kh, (value,Wv)->g_vh
__global__ __launch_bounds__(256)
void proj_kernel(const float* __restrict__ query,
                 const float* __restrict__ key,
                 const float* __restrict__ value,
                 const float* __restrict__ Wq, const float* __restrict__ bq,
                 const float* __restrict__ Wk, const float* __restrict__ bk,
                 const float* __restrict__ Wv, const float* __restrict__ bv)
{
    int m = blockIdx.y;
    if (m == 0)      gemm64<false, true>(query, Wq, bq, g_qh, nullptr);
    else if (m == 1) gemm64<false, true>(key,   Wk, bk, g_kh, nullptr);
    else             gemm64<false, true>(value, Wv, bv, g_vh, nullptr);
}

// Final: (g_acc / den) @ Wo^T + bo -> d_out (fp32)
__global__ __launch_bounds__(256)
void final_kernel(const float* __restrict__ Wo,
                  const float* __restrict__ bo,
                  float* __restrict__ out)
{
    gemm64<true, false>(g_acc, Wo, bo, out, g_den);
}

// ---------------------------------------------------------------------------
// Edge kernel: per edge e, score_h = dot16(q[dst],k[src]) / 4; ex = exp(score);
// acc[dst] += ex_h * v[src]; den[dst][h] += ex_h.
// q/k/v stored fp16 (rows are single 128B sectors); math in fp32.
// Half-warp (16 lanes x 4 halves) per edge; no segment-max needed (fp32 safe).
// ---------------------------------------------------------------------------
__global__ void edge_kernel(const int* __restrict__ src,
                            const int* __restrict__ dst, int E)
{
    long long t = (long long)blockIdx.x * blockDim.x + threadIdx.x;
    int e    = (int)(t >> 4);
    int lane = threadIdx.x & 31;
    int sub  = lane & 15;          // lane within edge group
    bool valid = e < E;
    int s = 0, d = 0;
    if (valid) { s = src[e]; d = dst[e]; }

    uint2 qr = *(const uint2*)(g_qh + (size_t)d * DIMC + sub * 4);
    uint2 kr = *(const uint2*)(g_kh + (size_t)s * DIMC + sub * 4);
    float2 q0 = __half22float2(*(__half2*)&qr.x);
    float2 q1 = __half22float2(*(__half2*)&qr.y);
    float2 k0 = __half22float2(*(__half2*)&kr.x);
    float2 k1 = __half22float2(*(__half2*)&kr.y);
    float p = q0.x * k0.x + q0.y * k0.y + q1.x * k1.x + q1.y * k1.y;
    // reduce within 4-lane head group (head = sub/4, 16 dims = 4 lanes x 4)
    p += __shfl_xor_sync(0xffffffffu, p, 1);
    p += __shfl_xor_sync(0xffffffffu, p, 2);
    float ex = __expf(p * 0.25f);   // 1/sqrt(DK)=0.25; scores O(1), no max needed

    uint2 vr = *(const uint2*)(g_vh + (size_t)s * DIMC + sub * 4);
    float2 v0 = __half22float2(*(__half2*)&vr.x);
    float2 v1 = __half22float2(*(__half2*)&vr.y);
    if (valid) {
        float* ap = g_acc + (size_t)d * DIMC + sub * 4;
        asm volatile("red.global.add.v4.f32 [%0], {%1,%2,%3,%4};"
                     :: "l"(ap), "f"(ex * v0.x), "f"(ex * v0.y),
                        "f"(ex * v1.x), "f"(ex * v1.y) : "memory");
    }
    // one vector red for the 4 head denominators (lane sub==0 of each half-warp)
    int hb = lane & 16;
    float e0 = __shfl_sync(0xffffffffu, ex, hb + 0);
    float e1 = __shfl_sync(0xffffffffu, ex, hb + 4);
    float e2 = __shfl_sync(0xffffffffu, ex, hb + 8);
    float e3 = __shfl_sync(0xffffffffu, ex, hb + 12);
    if (valid && sub == 0) {
        float* dp = g_den + (size_t)d * HH;
        asm volatile("red.global.add.v4.f32 [%0], {%1,%2,%3,%4};"
                     :: "l"(dp), "f"(e0), "f"(e1), "f"(e2), "f"(e3) : "memory");
    }
}

// ---------------------------------------------------------------------------
extern "C" void kernel_launch(void* const* d_in, const int* in_sizes, int n_in,
                              void* d_out, int out_size)
{
    const float* query = (const float*)d_in[0];
    const float* key   = (const float*)d_in[1];
    const float* value = (const float*)d_in[2];
    const int*   src   = (const int*)d_in[3];
    const int*   dst   = (const int*)d_in[4];
    const float* Wq = (const float*)d_in[5];  const float* bq = (const float*)d_in[6];
    const float* Wk = (const float*)d_in[7];  const float* bk = (const float*)d_in[8];
    const float* Wv = (const float*)d_in[9];  const float* bv = (const float*)d_in[10];
    const float* Wo = (const float*)d_in[11]; const float* bo = (const float*)d_in[12];
    int E = in_sizes[3];

    zero_kernel<<<2048, 256>>>();

    dim3 pg((NN + 127) / 128, 3);
    proj_kernel<<<pg, 256>>>(query, key, value, Wq, bq, Wk, bk, Wv, bv);

    long long ethreads = (long long)E * 16;
    int eblocks = (int)((ethreads + 255) / 256);
    edge_kernel<<<eblocks, 256>>>(src, dst, E);

    final_kernel<<<(NN + 127) / 128, 256>>>(Wo, bo, (float*)d_out);
}

// round 7
// speedup vs baseline: 5.2307x; 1.1349x over previous
#include <cuda_runtime.h>
#include <cuda_fp16.h>

#define NN   100000
#define DIMC 64
#define HH   4

// Scratch (allocation-free rule: __device__ globals)
__device__ __half g_qh[NN * DIMC];
__device__ __half g_kh[NN * DIMC];
__device__ __half g_vh[NN * DIMC];
__device__ float  g_acc[NN * DIMC];
__device__ float  g_den[NN * HH];

// ---------------------------------------------------------------------------
// Zero the accumulators
// ---------------------------------------------------------------------------
__global__ void zero_kernel() {
    int i = blockIdx.x * blockDim.x + threadIdx.x;
    int stride = gridDim.x * blockDim.x;
    float4 z = make_float4(0.f, 0.f, 0.f, 0.f);
    const int n4 = (NN * DIMC) / 4;
    for (int j = i; j < n4; j += stride) ((float4*)g_acc)[j] = z;
    const int nd = (NN * HH) / 4;
    for (int j = i; j < nd; j += stride) ((float4*)g_den)[j] = z;
}

// ---------------------------------------------------------------------------
// Tensor-core GEMM (3xTF32): out[node] = X[node] @ W^T + b, fp32 accuracy.
// mma.sync.m16n8k8.row.col: A = X tile (row-major m x k), B col-major k x n
// means b[k][n] = W[n][k] -> W rows feed B directly, no transpose.
// 3-term split: Ahi*Bhi + Alo*Bhi + Ahi*Blo (drops only (1e-4)^2 term).
// Block: 256 thr; tile 64 rows x 64 cols; warp = 16 rows x 32 cols.
// smem: sX fp32 + sWhi/sWlo (pre-split tf32) = 48 KB, all XOR-swizzled on
// 16B granules so fragment loads are bank-conflict-free.
// DIV_DEN: divide X by per-head softmax denominator during load.
// OUT_HALF: round result to __half on store (q/k/v scratch).
// ---------------------------------------------------------------------------
__device__ __forceinline__ unsigned f2tf32(float x) {
    unsigned r;
    asm("cvt.rna.tf32.f32 %0, %1;" : "=r"(r) : "f"(x));
    return r;
}

__device__ __forceinline__ void mma_tf32(float* c, const unsigned* a,
                                         unsigned b0, unsigned b1) {
    asm volatile(
        "mma.sync.aligned.m16n8k8.row.col.f32.tf32.tf32.f32 "
        "{%0,%1,%2,%3},{%4,%5,%6,%7},{%8,%9},{%0,%1,%2,%3};"
        : "+f"(c[0]), "+f"(c[1]), "+f"(c[2]), "+f"(c[3])
        : "r"(a[0]), "r"(a[1]), "r"(a[2]), "r"(a[3]), "r"(b0), "r"(b1));
}

template <bool DIV_DEN, bool OUT_HALF>
__device__ __forceinline__ void gemm_tc(const float* __restrict__ X,
                                        const float* __restrict__ W,
                                        const float* __restrict__ bias,
                                        void* __restrict__ out,
                                        const float* __restrict__ den)
{
    __shared__ float sX[64 * 64];     // 16 KB fp32 tile (later reused for C)
    __shared__ float sWhi[64 * 64];   // 16 KB tf32-hi bit patterns
    __shared__ float sWlo[64 * 64];   // 16 KB tf32-lo bit patterns

    int tid  = threadIdx.x;
    int base = blockIdx.x * 64;

    // --- W load + hi/lo split, swizzled: granule(c,k4) = c*16 + (k4 ^ (c&15))
#pragma unroll
    for (int i = 0; i < 4; i++) {
        int idx = tid + i * 256;          // float4 index 0..1023
        int c   = idx >> 4;
        int k4  = idx & 15;
        float4 w = ((const float4*)W)[idx];
        uint4 h, l;
        h.x = f2tf32(w.x); h.y = f2tf32(w.y);
        h.z = f2tf32(w.z); h.w = f2tf32(w.w);
        l.x = f2tf32(w.x - __uint_as_float(h.x));
        l.y = f2tf32(w.y - __uint_as_float(h.y));
        l.z = f2tf32(w.z - __uint_as_float(h.z));
        l.w = f2tf32(w.w - __uint_as_float(h.w));
        int g = c * 16 + (k4 ^ (c & 15));
        ((uint4*)sWhi)[g] = h;
        ((uint4*)sWlo)[g] = l;
    }

    // --- X tile load (fp32), swizzled; optional denominator divide
#pragma unroll
    for (int i = 0; i < 4; i++) {
        int idx  = tid + i * 256;
        int row  = idx >> 4;
        int k4   = idx & 15;
        int node = base + row;
        float4 xv = make_float4(0.f, 0.f, 0.f, 0.f);
        if (node < NN) {
            xv = ((const float4*)(X + (size_t)node * DIMC))[k4];
            if (DIV_DEN) {
                float dd  = den[node * HH + (k4 >> 2)];   // head = (4*k4)/16
                float inv = (dd > 0.f) ? (1.f / dd) : 0.f;
                xv.x *= inv; xv.y *= inv; xv.z *= inv; xv.w *= inv;
            }
        }
        ((float4*)sX)[row * 16 + (k4 ^ (row & 15))] = xv;
    }
    __syncthreads();

    int lane = tid & 31, warp = tid >> 5;
    int rowg = warp >> 1;          // 0..3 : rows rowg*16..+15
    int colh = warp & 1;           // 0..1 : cols colh*32..+31
    int gid  = lane >> 2;          // 0..7
    int tig  = lane & 3;           // 0..3
    int r0   = rowg * 16 + gid;
    int r1   = r0 + 8;

    float acc[4][4];
#pragma unroll
    for (int n = 0; n < 4; n++)
#pragma unroll
        for (int j = 0; j < 4; j++) acc[n][j] = 0.f;

#pragma unroll
    for (int ks = 0; ks < 8; ks++) {
        int g0 = 2 * ks;          // k granule of k = ks*8 + tig
        int g1 = 2 * ks + 1;      // k granule of k = ks*8 + tig + 4
        // A fragment: a0(r0,k0) a1(r1,k0) a2(r0,k1) a3(r1,k1)
        float a0f = sX[(r0 * 16 + (g0 ^ (r0 & 15))) * 4 + tig];
        float a1f = sX[(r1 * 16 + (g0 ^ (r1 & 15))) * 4 + tig];
        float a2f = sX[(r0 * 16 + (g1 ^ (r0 & 15))) * 4 + tig];
        float a3f = sX[(r1 * 16 + (g1 ^ (r1 & 15))) * 4 + tig];
        unsigned ah[4], al[4];
        ah[0] = f2tf32(a0f); al[0] = f2tf32(a0f - __uint_as_float(ah[0]));
        ah[1] = f2tf32(a1f); al[1] = f2tf32(a1f - __uint_as_float(ah[1]));
        ah[2] = f2tf32(a2f); al[2] = f2tf32(a2f - __uint_as_float(ah[2]));
        ah[3] = f2tf32(a3f); al[3] = f2tf32(a3f - __uint_as_float(ah[3]));
#pragma unroll
        for (int n = 0; n < 4; n++) {
            int c = colh * 32 + n * 8 + gid;
            int gb0 = (c * 16 + (g0 ^ (c & 15))) * 4 + tig;
            int gb1 = (c * 16 + (g1 ^ (c & 15))) * 4 + tig;
            unsigned bh0 = ((const unsigned*)sWhi)[gb0];
            unsigned bh1 = ((const unsigned*)sWhi)[gb1];
            unsigned bl0 = ((const unsigned*)sWlo)[gb0];
            unsigned bl1 = ((const unsigned*)sWlo)[gb1];
            mma_tf32(acc[n], ah, bh0, bh1);
            mma_tf32(acc[n], al, bh0, bh1);
            mma_tf32(acc[n], ah, bl0, bl1);
        }
    }

    // --- stage C into sX (swizzled), then coalesced writeback with bias
    __syncthreads();
#pragma unroll
    for (int n = 0; n < 4; n++) {
        int col = colh * 32 + n * 8 + 2 * tig;   // col%4 in {0,2}: pair fits granule
        int g   = col >> 2;
        int o   = col & 3;
        sX[(r0 * 16 + (g ^ (r0 & 15))) * 4 + o]     = acc[n][0];
        sX[(r0 * 16 + (g ^ (r0 & 15))) * 4 + o + 1] = acc[n][1];
        sX[(r1 * 16 + (g ^ (r1 & 15))) * 4 + o]     = acc[n][2];
        sX[(r1 * 16 + (g ^ (r1 & 15))) * 4 + o + 1] = acc[n][3];
    }
    __syncthreads();

#pragma unroll
    for (int i = 0; i < 4; i++) {
        int idx  = tid + i * 256;
        int row  = idx >> 4;
        int k4   = idx & 15;
        int node = base + row;
        if (node >= NN) continue;
        float4 v  = ((const float4*)sX)[row * 16 + (k4 ^ (row & 15))];
        float4 bb = ((const float4*)bias)[k4];
        v.x += bb.x; v.y += bb.y; v.z += bb.z; v.w += bb.w;
        if (OUT_HALF) {
            __half2 h0 = __float22half2_rn(make_float2(v.x, v.y));
            __half2 h1 = __float22half2_rn(make_float2(v.z, v.w));
            uint2 pk;
            pk.x = *(unsigned*)&h0;
            pk.y = *(unsigned*)&h1;
            *(uint2*)((__half*)out + (size_t)node * DIMC + k4 * 4) = pk;
        } else {
            *(float4*)((float*)out + (size_t)node * DIMC + k4 * 4) = v;
        }
    }
}

// Projections: blockIdx.y selects (query,Wq)->g_qh, (key,Wk)->g_kh, (value,Wv)->g_vh
__global__ __launch_bounds__(256)
void proj_kernel(const float* __restrict__ query,
                 const float* __restrict__ key,
                 const float* __restrict__ value,
                 const float* __restrict__ Wq, const float* __restrict__ bq,
                 const float* __restrict__ Wk, const float* __restrict__ bk,
                 const float* __restrict__ Wv, const float* __restrict__ bv)
{
    int m = blockIdx.y;
    if (m == 0)      gemm_tc<false, true>(query, Wq, bq, g_qh, nullptr);
    else if (m == 1) gemm_tc<false, true>(key,   Wk, bk, g_kh, nullptr);
    else             gemm_tc<false, true>(value, Wv, bv, g_vh, nullptr);
}

// Final: (g_acc / den) @ Wo^T + bo -> d_out (fp32)
__global__ __launch_bounds__(256)
void final_kernel(const float* __restrict__ Wo,
                  const float* __restrict__ bo,
                  float* __restrict__ out)
{
    gemm_tc<true, false>(g_acc, Wo, bo, out, g_den);
}

// ---------------------------------------------------------------------------
// Edge kernel: per edge e, score_h = dot16(q[dst],k[src]) / 4; ex = exp(score);
// acc[dst] += ex_h * v[src]; den[dst][h] += ex_h.
// q/k/v stored fp16 (rows are single 128B sectors); math in fp32.
// Half-warp (16 lanes x 4 halves) per edge; no segment-max needed (fp32 safe).
// ---------------------------------------------------------------------------
__global__ void edge_kernel(const int* __restrict__ src,
                            const int* __restrict__ dst, int E)
{
    long long t = (long long)blockIdx.x * blockDim.x + threadIdx.x;
    int e    = (int)(t >> 4);
    int lane = threadIdx.x & 31;
    int sub  = lane & 15;          // lane within edge group
    bool valid = e < E;
    int s = 0, d = 0;
    if (valid) { s = src[e]; d = dst[e]; }

    uint2 qr = *(const uint2*)(g_qh + (size_t)d * DIMC + sub * 4);
    uint2 kr = *(const uint2*)(g_kh + (size_t)s * DIMC + sub * 4);
    float2 q0 = __half22float2(*(__half2*)&qr.x);
    float2 q1 = __half22float2(*(__half2*)&qr.y);
    float2 k0 = __half22float2(*(__half2*)&kr.x);
    float2 k1 = __half22float2(*(__half2*)&kr.y);
    float p = q0.x * k0.x + q0.y * k0.y + q1.x * k1.x + q1.y * k1.y;
    // reduce within 4-lane head group (head = sub/4, 16 dims = 4 lanes x 4)
    p += __shfl_xor_sync(0xffffffffu, p, 1);
    p += __shfl_xor_sync(0xffffffffu, p, 2);
    float ex = __expf(p * 0.25f);   // 1/sqrt(DK)=0.25; scores O(1), no max needed

    uint2 vr = *(const uint2*)(g_vh + (size_t)s * DIMC + sub * 4);
    float2 v0 = __half22float2(*(__half2*)&vr.x);
    float2 v1 = __half22float2(*(__half2*)&vr.y);
    if (valid) {
        float* ap = g_acc + (size_t)d * DIMC + sub * 4;
        asm volatile("red.global.add.v4.f32 [%0], {%1,%2,%3,%4};"
                     :: "l"(ap), "f"(ex * v0.x), "f"(ex * v0.y),
                        "f"(ex * v1.x), "f"(ex * v1.y) : "memory");
    }
    // one vector red for the 4 head denominators (lane sub==0 of each half-warp)
    int hb = lane & 16;
    float e0 = __shfl_sync(0xffffffffu, ex, hb + 0);
    float e1 = __shfl_sync(0xffffffffu, ex, hb + 4);
    float e2 = __shfl_sync(0xffffffffu, ex, hb + 8);
    float e3 = __shfl_sync(0xffffffffu, ex, hb + 12);
    if (valid && sub == 0) {
        float* dp = g_den + (size_t)d * HH;
        asm volatile("red.global.add.v4.f32 [%0], {%1,%2,%3,%4};"
                     :: "l"(dp), "f"(e0), "f"(e1), "f"(e2), "f"(e3) : "memory");
    }
}

// ---------------------------------------------------------------------------
extern "C" void kernel_launch(void* const* d_in, const int* in_sizes, int n_in,
                              void* d_out, int out_size)
{
    const float* query = (const float*)d_in[0];
    const float* key   = (const float*)d_in[1];
    const float* value = (const float*)d_in[2];
    const int*   src   = (const int*)d_in[3];
    const int*   dst   = (const int*)d_in[4];
    const float* Wq = (const float*)d_in[5];  const float* bq = (const float*)d_in[6];
    const float* Wk = (const float*)d_in[7];  const float* bk = (const float*)d_in[8];
    const float* Wv = (const float*)d_in[9];  const float* bv = (const float*)d_in[10];
    const float* Wo = (const float*)d_in[11]; const float* bo = (const float*)d_in[12];
    int E = in_sizes[3];

    zero_kernel<<<2048, 256>>>();

    dim3 pg((NN + 63) / 64, 3);
    proj_kernel<<<pg, 256>>>(query, key, value, Wq, bq, Wk, bk, Wv, bv);

    long long ethreads = (long long)E * 16;
    int eblocks = (int)((ethreads + 255) / 256);
    edge_kernel<<<eblocks, 256>>>(src, dst, E);

    final_kernel<<<(NN + 63) / 64, 256>>>(Wo, bo, (float*)d_out);
}

// round 9
// speedup vs baseline: 5.3761x; 1.0278x over previous
#include <cuda_runtime.h>
#include <cuda_fp16.h>

#define NN   100000
#define DIMC 64
#define HH   4

// Scratch (allocation-free rule: __device__ globals)
__device__ __half g_qh[NN * DIMC];
__device__ __half g_kh[NN * DIMC];
__device__ __half g_vh[NN * DIMC];
__device__ float  g_acc[NN * DIMC];
__device__ float  g_den[NN * HH];

// Pre-split, fragment-ordered W images (hi/lo tf32), one per matrix
// (0=Wq, 1=Wk, 2=Wv, 3=Wo). Layout: [(nt*8 + ks)*32 + lane] holds the uint2
// B-fragment {W[c][k0], W[c][k0+4]} with c = nt*8 + lane/4, k0 = ks*8 + lane%4.
__device__ uint2 g_Bhi[4][2048];
__device__ uint2 g_Blo[4][2048];

__device__ __forceinline__ unsigned f2tf32(float x) {
    unsigned r;
    asm("cvt.rna.tf32.f32 %0, %1;" : "=r"(r) : "f"(x));
    return r;
}

// ---------------------------------------------------------------------------
// Pack kernel: split each W into tf32 hi/lo and store in B-fragment order.
// grid = 4 (one block per matrix), block = 256.
// ---------------------------------------------------------------------------
__global__ void pack_kernel(const float* __restrict__ Wq,
                            const float* __restrict__ Wk,
                            const float* __restrict__ Wv,
                            const float* __restrict__ Wo)
{
    int m = blockIdx.x;
    const float* W = (m == 0) ? Wq : (m == 1) ? Wk : (m == 2) ? Wv : Wo;
#pragma unroll
    for (int i = 0; i < 8; i++) {
        int idx  = threadIdx.x + i * 256;     // 0..2047
        int lane = idx & 31;
        int ks   = (idx >> 5) & 7;
        int nt   = idx >> 8;
        int c    = nt * 8 + (lane >> 2);
        int k0   = ks * 8 + (lane & 3);
        float w0 = W[c * DIMC + k0];
        float w1 = W[c * DIMC + k0 + 4];
        uint2 h, l;
        h.x = f2tf32(w0); h.y = f2tf32(w1);
        l.x = f2tf32(w0 - __uint_as_float(h.x));
        l.y = f2tf32(w1 - __uint_as_float(h.y));
        g_Bhi[m][idx] = h;
        g_Blo[m][idx] = l;
    }
}

// ---------------------------------------------------------------------------
// Zero the accumulators
// ---------------------------------------------------------------------------
__global__ void zero_kernel() {
    int i = blockIdx.x * blockDim.x + threadIdx.x;
    int stride = gridDim.x * blockDim.x;
    float4 z = make_float4(0.f, 0.f, 0.f, 0.f);
    const int n4 = (NN * DIMC) / 4;
    for (int j = i; j < n4; j += stride) ((float4*)g_acc)[j] = z;
    const int nd = (NN * HH) / 4;
    for (int j = i; j < nd; j += stride) ((float4*)g_den)[j] = z;
}

// ---------------------------------------------------------------------------
// Tensor-core GEMM (3xTF32): out[node] = X[node] @ W^T + b, fp32 accuracy.
// B comes pre-split and fragment-ordered from g_Bhi/g_Blo -> inner-loop B
// loads are linear LDS.64 (no swizzle math, no per-block cvt).
// Block: 256 thr; tile 64 rows x 64 cols; warp = 16 rows x 32 cols.
// ---------------------------------------------------------------------------
__device__ __forceinline__ void mma_tf32(float* c, const unsigned* a,
                                         unsigned b0, unsigned b1) {
    asm volatile(
        "mma.sync.aligned.m16n8k8.row.col.f32.tf32.tf32.f32 "
        "{%0,%1,%2,%3},{%4,%5,%6,%7},{%8,%9},{%0,%1,%2,%3};"
        : "+f"(c[0]), "+f"(c[1]), "+f"(c[2]), "+f"(c[3])
        : "r"(a[0]), "r"(a[1]), "r"(a[2]), "r"(a[3]), "r"(b0), "r"(b1));
}

template <bool DIV_DEN, bool OUT_HALF>
__device__ __forceinline__ void gemm_tc(const float* __restrict__ X,
                                        int wsel,
                                        const float* __restrict__ bias,
                                        void* __restrict__ out,
                                        const float* __restrict__ den)
{
    __shared__ float sX[64 * 64];     // 16 KB fp32 tile (later reused for C)
    __shared__ uint2 sBhi[2048];      // 16 KB packed tf32-hi fragments
    __shared__ uint2 sBlo[2048];      // 16 KB packed tf32-lo fragments

    int tid  = threadIdx.x;
    int base = blockIdx.x * 64;

    // --- packed B images: coalesced copy from global
#pragma unroll
    for (int i = 0; i < 8; i++) {
        int idx = tid + i * 256;
        sBhi[idx] = g_Bhi[wsel][idx];
        sBlo[idx] = g_Blo[wsel][idx];
    }

    // --- X tile load (fp32), swizzled; optional denominator divide
#pragma unroll
    for (int i = 0; i < 4; i++) {
        int idx  = tid + i * 256;
        int row  = idx >> 4;
        int k4   = idx & 15;
        int node = base + row;
        float4 xv = make_float4(0.f, 0.f, 0.f, 0.f);
        if (node < NN) {
            xv = ((const float4*)(X + (size_t)node * DIMC))[k4];
            if (DIV_DEN) {
                float dd  = den[node * HH + (k4 >> 2)];   // head = (4*k4)/16
                float inv = (dd > 0.f) ? (1.f / dd) : 0.f;
                xv.x *= inv; xv.y *= inv; xv.z *= inv; xv.w *= inv;
            }
        }
        ((float4*)sX)[row * 16 + (k4 ^ (row & 15))] = xv;
    }
    __syncthreads();

    int lane = tid & 31, warp = tid >> 5;
    int rowg = warp >> 1;          // 0..3 : rows rowg*16..+15
    int colh = warp & 1;           // 0..1 : n-tiles colh*4 .. colh*4+3
    int gid  = lane >> 2;          // 0..7
    int tig  = lane & 3;           // 0..3
    int r0   = rowg * 16 + gid;
    int r1   = r0 + 8;

    float acc[4][4];
#pragma unroll
    for (int n = 0; n < 4; n++)
#pragma unroll
        for (int j = 0; j < 4; j++) acc[n][j] = 0.f;

#pragma unroll
    for (int ks = 0; ks < 8; ks++) {
        int g0 = 2 * ks;          // k granule of k = ks*8 + tig
        int g1 = 2 * ks + 1;      // k granule of k = ks*8 + tig + 4
        // A fragment: a0(r0,k0) a1(r1,k0) a2(r0,k1) a3(r1,k1)
        float a0f = sX[(r0 * 16 + (g0 ^ (r0 & 15))) * 4 + tig];
        float a1f = sX[(r1 * 16 + (g0 ^ (r1 & 15))) * 4 + tig];
        float a2f = sX[(r0 * 16 + (g1 ^ (r0 & 15))) * 4 + tig];
        float a3f = sX[(r1 * 16 + (g1 ^ (r1 & 15))) * 4 + tig];
        unsigned ah[4], al[4];
        ah[0] = f2tf32(a0f); al[0] = f2tf32(a0f - __uint_as_float(ah[0]));
        ah[1] = f2tf32(a1f); al[1] = f2tf32(a1f - __uint_as_float(ah[1]));
        ah[2] = f2tf32(a2f); al[2] = f2tf32(a2f - __uint_as_float(ah[2]));
        ah[3] = f2tf32(a3f); al[3] = f2tf32(a3f - __uint_as_float(ah[3]));
#pragma unroll
        for (int n = 0; n < 4; n++) {
            int nt = colh * 4 + n;
            int bi = (nt * 8 + ks) * 32 + lane;   // linear, strength-reducible
            uint2 bh = sBhi[bi];
            uint2 bl = sBlo[bi];
            mma_tf32(acc[n], ah, bh.x, bh.y);
            mma_tf32(acc[n], al, bh.x, bh.y);
            mma_tf32(acc[n], ah, bl.x, bl.y);
        }
    }

    // --- stage C into sX (swizzled), then coalesced writeback with bias
    __syncthreads();
#pragma unroll
    for (int n = 0; n < 4; n++) {
        int col = (colh * 4 + n) * 8 + 2 * tig;  // col%4 in {0,2}: pair fits granule
        int g   = col >> 2;
        int o   = col & 3;
        sX[(r0 * 16 + (g ^ (r0 & 15))) * 4 + o]     = acc[n][0];
        sX[(r0 * 16 + (g ^ (r0 & 15))) * 4 + o + 1] = acc[n][1];
        sX[(r1 * 16 + (g ^ (r1 & 15))) * 4 + o]     = acc[n][2];
        sX[(r1 * 16 + (g ^ (r1 & 15))) * 4 + o + 1] = acc[n][3];
    }
    __syncthreads();

#pragma unroll
    for (int i = 0; i < 4; i++) {
        int idx  = tid + i * 256;
        int row  = idx >> 4;
        int k4   = idx & 15;
        int node = base + row;
        if (node >= NN) continue;
        float4 v  = ((const float4*)sX)[row * 16 + (k4 ^ (row & 15))];
        float4 bb = ((const float4*)bias)[k4];
        v.x += bb.x; v.y += bb.y; v.z += bb.z; v.w += bb.w;
        if (OUT_HALF) {
            __half2 h0 = __float22half2_rn(make_float2(v.x, v.y));
            __half2 h1 = __float22half2_rn(make_float2(v.z, v.w));
            uint2 pk;
            pk.x = *(unsigned*)&h0;
            pk.y = *(unsigned*)&h1;
            *(uint2*)((__half*)out + (size_t)node * DIMC + k4 * 4) = pk;
        } else {
            *(float4*)((float*)out + (size_t)node * DIMC + k4 * 4) = v;
        }
    }
}

// Projections: blockIdx.y selects (query,0)->g_qh, (key,1)->g_kh, (value,2)->g_vh
__global__ __launch_bounds__(256)
void proj_kernel(const float* __restrict__ query,
                 const float* __restrict__ key,
                 const float* __restrict__ value,
                 const float* __restrict__ bq,
                 const float* __restrict__ bk,
                 const float* __restrict__ bv)
{
    int m = blockIdx.y;
    if (m == 0)      gemm_tc<false, true>(query, 0, bq, g_qh, nullptr);
    else if (m == 1) gemm_tc<false, true>(key,   1, bk, g_kh, nullptr);
    else             gemm_tc<false, true>(value, 2, bv, g_vh, nullptr);
}

// Final: (g_acc / den) @ Wo^T + bo -> d_out (fp32)
__global__ __launch_bounds__(256)
void final_kernel(const float* __restrict__ bo,
                  float* __restrict__ out)
{
    gemm_tc<true, false>(g_acc, 3, bo, out, g_den);
}

// ---------------------------------------------------------------------------
// Edge kernel: per edge e, score_h = dot16(q[dst],k[src]) / 4; ex = exp(score);
// acc[dst] += ex_h * v[src]; den[dst][h] += ex_h.
// q/k/v stored fp16 (rows are single 128B sectors); math in fp32.
// Half-warp (16 lanes x 4 halves) per edge; no segment-max needed (fp32 safe).
// ---------------------------------------------------------------------------
__global__ void edge_kernel(const int* __restrict__ src,
                            const int* __restrict__ dst, int E)
{
    long long t = (long long)blockIdx.x * blockDim.x + threadIdx.x;
    int e    = (int)(t >> 4);
    int lane = threadIdx.x & 31;
    int sub  = lane & 15;          // lane within edge group
    bool valid = e < E;
    int s = 0, d = 0;
    if (valid) { s = src[e]; d = dst[e]; }

    uint2 qr = *(const uint2*)(g_qh + (size_t)d * DIMC + sub * 4);
    uint2 kr = *(const uint2*)(g_kh + (size_t)s * DIMC + sub * 4);
    float2 q0 = __half22float2(*(__half2*)&qr.x);
    float2 q1 = __half22float2(*(__half2*)&qr.y);
    float2 k0 = __half22float2(*(__half2*)&kr.x);
    float2 k1 = __half22float2(*(__half2*)&kr.y);
    float p = q0.x * k0.x + q0.y * k0.y + q1.x * k1.x + q1.y * k1.y;
    // reduce within 4-lane head group (head = sub/4, 16 dims = 4 lanes x 4)
    p += __shfl_xor_sync(0xffffffffu, p, 1);
    p += __shfl_xor_sync(0xffffffffu, p, 2);
    float ex = __expf(p * 0.25f);   // 1/sqrt(DK)=0.25; scores O(1), no max needed

    uint2 vr = *(const uint2*)(g_vh + (size_t)s * DIMC + sub * 4);
    float2 v0 = __half22float2(*(__half2*)&vr.x);
    float2 v1 = __half22float2(*(__half2*)&vr.y);
    if (valid) {
        float* ap = g_acc + (size_t)d * DIMC + sub * 4;
        asm volatile("red.global.add.v4.f32 [%0], {%1,%2,%3,%4};"
                     :: "l"(ap), "f"(ex * v0.x), "f"(ex * v0.y),
                        "f"(ex * v1.x), "f"(ex * v1.y) : "memory");
    }
    // one vector red for the 4 head denominators (lane sub==0 of each half-warp)
    int hb = lane & 16;
    float e0 = __shfl_sync(0xffffffffu, ex, hb + 0);
    float e1 = __shfl_sync(0xffffffffu, ex, hb + 4);
    float e2 = __shfl_sync(0xffffffffu, ex, hb + 8);
    float e3 = __shfl_sync(0xffffffffu, ex, hb + 12);
    if (valid && sub == 0) {
        float* dp = g_den + (size_t)d * HH;
        asm volatile("red.global.add.v4.f32 [%0], {%1,%2,%3,%4};"
                     :: "l"(dp), "f"(e0), "f"(e1), "f"(e2), "f"(e3) : "memory");
    }
}

// ---------------------------------------------------------------------------
extern "C" void kernel_launch(void* const* d_in, const int* in_sizes, int n_in,
                              void* d_out, int out_size)
{
    const float* query = (const float*)d_in[0];
    const float* key   = (const float*)d_in[1];
    const float* value = (const float*)d_in[2];
    const int*   src   = (const int*)d_in[3];
    const int*   dst   = (const int*)d_in[4];
    const float* Wq = (const float*)d_in[5];  const float* bq = (const float*)d_in[6];
    const float* Wk = (const float*)d_in[7];  const float* bk = (const float*)d_in[8];
    const float* Wv = (const float*)d_in[9];  const float* bv = (const float*)d_in[10];
    const float* Wo = (const float*)d_in[11]; const float* bo = (const float*)d_in[12];
    int E = in_sizes[3];

    pack_kernel<<<4, 256>>>(Wq, Wk, Wv, Wo);
    zero_kernel<<<2048, 256>>>();

    dim3 pg((NN + 63) / 64, 3);
    proj_kernel<<<pg, 256>>>(query, key, value, bq, bk, bv);

    long long ethreads = (long long)E * 16;
    int eblocks = (int)((ethreads + 255) / 256);
    edge_kernel<<<eblocks, 256>>>(src, dst, E);

    final_kernel<<<(NN + 63) / 64, 256>>>(bo, (float*)d_out);
}